// round 5
// baseline (speedup 1.0000x reference)
#include <cuda_runtime.h>
#include <cuda_bf16.h>

// VQLayer forward == identity copy of `inputs` (verified R1/R2: rel_err 1.1e-8).
//   quantized = closest + stop_gradient(inputs - closest) == inputs (forward value).
//
// R2 post-mortem: two very different SM copy-kernel shapes both pinned at
// ~6.1 us GPU-side with ALL pipes <18% utilized => fixed launch-ramp/drain
// floor dominates (pure transfer ~2.4 us at LTS cap). R3: bypass the SM grid
// entirely with a driver D2D memcpy node (explicitly allowed by harness rules,
// graph-capturable). Copy engine path has a different (lower) ramp profile.

extern "C" void kernel_launch(void* const* d_in, const int* in_sizes, int n_in,
                              void* d_out, int out_size) {
    // d_in[0]: inputs [32,32,32,64] float32 -> 2097152 elements = 8 MB
    // Output dtype is float32 (same as input); forward value is the identity.
    cudaMemcpyAsync(d_out, d_in[0], (size_t)out_size * sizeof(float),
                    cudaMemcpyDeviceToDevice, 0);
}